// round 12
// baseline (speedup 1.0000x reference)
#include <cuda_runtime.h>
#include <math.h>

// Problem dims
#define BB   64
#define TT   256
#define HD   768
#define HHD  384
#define G4   1536       // 4*HHD
#define BT   (BB*TT)
#define NK   9
#define RECBLK 96       // persistent recurrence blocks (<= #SMs, all co-resident)

// ---------------- device scratch (static, no allocation) ----------------
__device__ float g_G[2 * BT * G4];        // input projections per dir (permuted gate cols)
__device__ float g_h0[BT * HD];           // layer0 output (concat fwd|bwd), row-major
__device__ float g_h1[BT * HD];           // layer1 output, row-major
__device__ float g_hT[TT * 2 * HHD * BB]; // transposed h: [t][dir][k][b] for recurrence reads
__device__ float g_Wih_p[2 * G4 * HD];    // permuted input weights  (row n' = j*4+gate)
__device__ float g_Whh_t[2 * HHD * G4];   // transposed recurrent weights [dir][k][n']
__device__ float g_bias_p[2 * G4];        // permuted bih+bhh
__device__ float g_em[BT * NK];           // emissions
__device__ float g_lp[BB];                // per-batch loglik
__device__ unsigned g_bar[2][TT];         // per-(layer,step) barrier counters

// ---------------- barrier counter zeroing (runs first in graph) ----------------
__global__ void bar_init() {
    int i = threadIdx.x;              // 256 threads
    g_bar[0][i] = 0;
    g_bar[1][i] = 0;
}

// ---------------- weight permutation: n' = j*4 + gate ----------------
__global__ void prep_kernel(const float* __restrict__ wf, const float* __restrict__ hf,
                            const float* __restrict__ bif, const float* __restrict__ bhf,
                            const float* __restrict__ wb, const float* __restrict__ hb,
                            const float* __restrict__ bib, const float* __restrict__ bhb) {
    int blk = blockIdx.x;                 // 0 .. 2*G4-1
    int dir = blk / G4;
    int np  = blk - dir * G4;
    const float* wih = dir ? wb  : wf;
    const float* whh = dir ? hb  : hf;
    const float* bi  = dir ? bib : bif;
    const float* bh  = dir ? bhb : bhf;
    int j = np >> 2, gate = np & 3;
    int r = gate * HHD + j;               // original row in [4H, *]
    float* dwi = g_Wih_p + (size_t)(dir * G4 + np) * HD;
    const float* swi = wih + (size_t)r * HD;
    for (int i = threadIdx.x; i < HD; i += 256) dwi[i] = swi[i];
    const float* swh = whh + (size_t)r * HHD;
    for (int i = threadIdx.x; i < HHD; i += 256)
        g_Whh_t[((size_t)dir * HHD + i) * G4 + np] = swh[i];   // [dir][k][n']
    if (threadIdx.x == 0) g_bias_p[dir * G4 + np] = bi[r] + bh[r];
}

// ---------------- input projection SGEMM: G = X @ Wp^T + bias ----------------
// 128x128 tile, kt=16, 256 threads, 8x8 microtile (split 4+4 at +64 offsets)
__global__ void __launch_bounds__(256, 2) gemm_proj(const float* __restrict__ Xext, int layer) {
    __shared__ __align__(16) float As[16][132];
    __shared__ __align__(16) float Bs[16][132];
    int dir = blockIdx.z;
    const float* X    = layer ? g_h0 : Xext;
    const float* Wp   = g_Wih_p  + (size_t)dir * G4 * HD;
    const float* bias = g_bias_p + dir * G4;
    float* out        = g_G      + (size_t)dir * BT * G4;
    int m0 = blockIdx.y * 128, n0 = blockIdx.x * 128;
    int tid = threadIdx.x;
    int tx = tid & 15, ty = tid >> 4;      // tx -> n quads, ty -> m quads
    float acc[8][8] = {};
    for (int k0 = 0; k0 < HD; k0 += 16) {
#pragma unroll
        for (int i = 0; i < 8; i++) {
            int lin = tid + i * 256; int r = lin >> 4, c = lin & 15;
            As[c][r] = X [(size_t)(m0 + r) * HD + k0 + c];
            Bs[c][r] = Wp[(size_t)(n0 + r) * HD + k0 + c];
        }
        __syncthreads();
#pragma unroll
        for (int k = 0; k < 16; k++) {
            float4 a0 = *(const float4*)&As[k][ty * 4];
            float4 a1 = *(const float4*)&As[k][ty * 4 + 64];
            float4 b0 = *(const float4*)&Bs[k][tx * 4];
            float4 b1 = *(const float4*)&Bs[k][tx * 4 + 64];
            float av[8] = {a0.x, a0.y, a0.z, a0.w, a1.x, a1.y, a1.z, a1.w};
            float bv[8] = {b0.x, b0.y, b0.z, b0.w, b1.x, b1.y, b1.z, b1.w};
#pragma unroll
            for (int i = 0; i < 8; i++)
#pragma unroll
                for (int j = 0; j < 8; j++)
                    acc[i][j] += av[i] * bv[j];
        }
        __syncthreads();
    }
    float4 bb0 = *(const float4*)&bias[n0 + tx * 4];
    float4 bb1 = *(const float4*)&bias[n0 + tx * 4 + 64];
#pragma unroll
    for (int i = 0; i < 8; i++) {
        int m = m0 + ((i < 4) ? (ty * 4 + i) : (ty * 4 + i - 4 + 64));
        float4 v0 = make_float4(acc[i][0] + bb0.x, acc[i][1] + bb0.y,
                                acc[i][2] + bb0.z, acc[i][3] + bb0.w);
        float4 v1 = make_float4(acc[i][4] + bb1.x, acc[i][5] + bb1.y,
                                acc[i][6] + bb1.z, acc[i][7] + bb1.w);
        *(float4*)&out[(size_t)m * G4 + n0 + tx * 4]      = v0;
        *(float4*)&out[(size_t)m * G4 + n0 + tx * 4 + 64] = v1;
    }
}

// ---------------- persistent recurrence kernel (v4) ----------------
// 96 blocks = (48 n-tiles x 2 dirs), 256 threads (8 warps, 2 per SMSP).
// Tile per block: ALL 64 batches x 32 gate-cols x full K=384, with an
// in-block K-split: kg=0 warps do k in [0,192), kg=1 warps k in [192,384),
// merged via an 8KB smem reduce each step. Microtile stays 4b x 4n'
// (2x LDS.128 per 16 FFMA, crossbar-balanced). 1 grid barrier per step.
#define WS 36
#define HS 68
#define RED_OFF (HHD*WS + HHD*HS)
#define REC_SMEM ((RED_OFF + 128*16) * 4)   /* 55296+104448+8192 = 167936 B */

__global__ void __launch_bounds__(256, 1) lstm_rec(int layer) {
    extern __shared__ __align__(16) float sm[];
    float* Wsm = sm;              // [384][WS]: Wsm[k][n]
    float* Hs  = sm + HHD * WS;   // [384][HS]: Hs[k][b]
    float* Red = sm + RED_OFF;    // [128][16]: k-split partials

    int tid = threadIdx.x;
    int lt  = tid & 127;               // position within k-group
    int kg  = tid >> 7;                // k-group 0/1
    int tx = lt & 7, ty = lt >> 3;     // tx: gate-quad (8), ty: batch-quad (16)
    int ntile = blockIdx.x, dir = blockIdx.y;
    int n0 = ntile * 32;
    int jj = ntile * 8 + tx;           // hidden unit index 0..383
    int kbase = kg * 192;
    float* hbuf = layer ? g_h1 : g_h0;

    // one-time coalesced Whh tile load from transposed copy
    const float* Wt = g_Whh_t + (size_t)dir * HHD * G4;
    for (int idx = tid; idx < HHD * 32; idx += 256) {
        int k = idx >> 5, n = idx & 31;
        Wsm[k * WS + n] = Wt[(size_t)k * G4 + n0 + n];
    }
    __syncthreads();

    const float* Gd = g_G + (size_t)dir * BT * G4;
    float c[4] = {0.f, 0.f, 0.f, 0.f};

    for (int t = 0; t < TT; t++) {
        int tt2 = dir ? (TT - 1 - t) : t;
        float acc[4][4] = {};
        if (t > 0) {
            int tp = dir ? (tt2 + 1) : (tt2 - 1);
            // coalesced full-tile load: g_hT[tp][dir][k][0..63] -> Hs[k][b]
            const float4* src = (const float4*)(g_hT + (size_t)(tp * 2 + dir) * HHD * BB);
#pragma unroll
            for (int i = 0; i < 24; i++) {            // 6144 float4 / 256 thr
                int f = i * 256 + tid;
                int k = f >> 4, bq = f & 15;
                *(float4*)&Hs[k * HS + bq * 4] = src[f];
            }
            __syncthreads();
#pragma unroll 8
            for (int kk = 0; kk < 192; kk++) {
                int k = kbase + kk;
                float4 w = *(const float4*)&Wsm[k * WS + tx * 4];
                float4 a = *(const float4*)&Hs[k * HS + ty * 4];
                acc[0][0] += a.x*w.x; acc[0][1] += a.x*w.y; acc[0][2] += a.x*w.z; acc[0][3] += a.x*w.w;
                acc[1][0] += a.y*w.x; acc[1][1] += a.y*w.y; acc[1][2] += a.y*w.z; acc[1][3] += a.y*w.w;
                acc[2][0] += a.z*w.x; acc[2][1] += a.z*w.y; acc[2][2] += a.z*w.z; acc[2][3] += a.z*w.w;
                acc[3][0] += a.w*w.x; acc[3][1] += a.w*w.y; acc[3][2] += a.w*w.z; acc[3][3] += a.w*w.w;
            }
            // k-split merge: kg=1 publishes, kg=0 accumulates
            if (kg) {
#pragma unroll
                for (int i = 0; i < 4; i++)
                    *(float4*)&Red[lt * 16 + i * 4] =
                        make_float4(acc[i][0], acc[i][1], acc[i][2], acc[i][3]);
            }
            __syncthreads();
            if (!kg) {
#pragma unroll
                for (int i = 0; i < 4; i++) {
                    float4 r = *(const float4*)&Red[lt * 16 + i * 4];
                    acc[i][0] += r.x; acc[i][1] += r.y; acc[i][2] += r.z; acc[i][3] += r.w;
                }
            }
        }
        // gate nonlinearity + cell update (kg=0 threads own the outputs)
        if (!kg) {
            float hv[4];
#pragma unroll
            for (int i = 0; i < 4; i++) {
                int b = ty * 4 + i;
                float4 g = *(const float4*)&Gd[((size_t)(b * TT + tt2)) * G4 + n0 + tx * 4];
                g.x += acc[i][0]; g.y += acc[i][1]; g.z += acc[i][2]; g.w += acc[i][3];
                float ig = 1.f / (1.f + expf(-g.x));
                float fg = 1.f / (1.f + expf(-g.y));
                float gg = tanhf(g.z);
                float og = 1.f / (1.f + expf(-g.w));
                float cn = fg * c[i] + ig * gg;
                c[i] = cn;
                hv[i] = og * tanhf(cn);
                hbuf[((size_t)(b * TT + tt2)) * HD + dir * HHD + jj] = hv[i];
            }
            *(float4*)&g_hT[((size_t)(tt2 * 2 + dir) * HHD + jj) * BB + ty * 4] =
                make_float4(hv[0], hv[1], hv[2], hv[3]);
        }

        if (t < TT - 1) {
            __threadfence();                 // release h writes
            __syncthreads();
            if (tid == 0) {
                atomicAdd(&g_bar[layer][t], 1u);
                while (((volatile unsigned*)g_bar[layer])[t] < RECBLK) {}
                __threadfence();             // acquire
            }
            __syncthreads();
        }
    }
}

// ---------------- emission FC: em = h1 @ fc_w^T + fc_b ----------------
__global__ void fc_kernel(const float* __restrict__ fcw, const float* __restrict__ fcb) {
    int m = blockIdx.x;
    int w = threadIdx.x >> 5, lane = threadIdx.x & 31;  // 9 warps
    const float* h  = g_h1 + (size_t)m * HD;
    const float* wr = fcw + (size_t)w * HD;
    float s = 0.f;
#pragma unroll
    for (int i = 0; i < HD / 32; i++) s += h[i * 32 + lane] * wr[i * 32 + lane];
#pragma unroll
    for (int o = 16; o; o >>= 1) s += __shfl_xor_sync(0xffffffffu, s, o);
    if (lane == 0) g_em[m * NK + w] = s + fcb[w];
}

// ---------------- CRF forward (summed loglik numerator & logZ) ----------------
__global__ void crf_fwd(const int* __restrict__ y, const float* __restrict__ start,
                        const float* __restrict__ trans, const float* __restrict__ endt) {
    int b = blockIdx.x; int lane = threadIdx.x;
    int k = lane < NK ? lane : NK - 1;
    float tr[NK];
#pragma unroll
    for (int p = 0; p < NK; p++) tr[p] = trans[p * NK + k];
    const float* emb = g_em + (size_t)b * TT * NK;
    float num = 0.f;
    if (lane == 0) {
        const int* yb = y + b * TT;
        int prev = yb[0];
        num = start[prev] + emb[prev];
        for (int t = 1; t < TT; t++) {
            int yt = yb[t];
            num += trans[prev * NK + yt] + emb[t * NK + yt];
            prev = yt;
        }
        num += endt[prev];
    }
    float alpha = start[k] + emb[k];
    for (int t = 1; t < TT; t++) {
        float av[NK]; float m = -1e30f;
#pragma unroll
        for (int p = 0; p < NK; p++) {
            av[p] = __shfl_sync(0xffffffffu, alpha, p) + tr[p];
            m = fmaxf(m, av[p]);
        }
        float s = 0.f;
#pragma unroll
        for (int p = 0; p < NK; p++) s += expf(av[p] - m);
        alpha = m + logf(s) + emb[t * NK + k];
    }
    float v = alpha + endt[k];
    float m2 = -1e30f; float vs[NK];
#pragma unroll
    for (int p = 0; p < NK; p++) {
        vs[p] = __shfl_sync(0xffffffffu, v, p);
        m2 = fmaxf(m2, vs[p]);
    }
    float s2 = 0.f;
#pragma unroll
    for (int p = 0; p < NK; p++) s2 += expf(vs[p] - m2);
    if (lane == 0) g_lp[b] = num - (m2 + logf(s2));
}

__global__ void finalize_loss(float* out) {
    if (threadIdx.x == 0) {
        float s = 0.f;
        for (int i = 0; i < BB; i++) s += g_lp[i];
        out[0] = s;
    }
}

// ---------------- Viterbi decode (first-max tie-break, matches jnp.argmax) ----------------
__global__ void viterbi_kernel(const float* __restrict__ start, const float* __restrict__ trans,
                               const float* __restrict__ endt, float* __restrict__ out) {
    __shared__ int hist[TT - 1][NK];
    int b = blockIdx.x; int lane = threadIdx.x;
    int k = lane < NK ? lane : NK - 1;
    float tr[NK];
#pragma unroll
    for (int p = 0; p < NK; p++) tr[p] = trans[p * NK + k];
    const float* emb = g_em + (size_t)b * TT * NK;
    float score = start[k] + emb[k];
    for (int t = 1; t < TT; t++) {
        float best = -1e30f; int arg = 0;
#pragma unroll
        for (int p = 0; p < NK; p++) {
            float v = __shfl_sync(0xffffffffu, score, p) + tr[p];
            if (v > best) { best = v; arg = p; }
        }
        if (lane < NK) hist[t - 1][lane] = arg;
        score = best + emb[t * NK + k];
    }
    float v = score + endt[k];
    float best = -1e30f; int last = 0;
#pragma unroll
    for (int p = 0; p < NK; p++) {
        float f = __shfl_sync(0xffffffffu, v, p);
        if (f > best) { best = f; last = p; }
    }
    __syncwarp();
    if (lane == 0) {
        float* ob = out + 1 + b * TT;
        int tag = last;
        ob[TT - 1] = (float)last;
        for (int t = TT - 2; t >= 0; t--) { tag = hist[t][tag]; ob[t] = (float)tag; }
    }
}

// ---------------- launch ----------------
extern "C" void kernel_launch(void* const* d_in, const int* in_sizes, int n_in,
                              void* d_out, int out_size) {
    const float* bert  = (const float*)d_in[0];
    const float* fcw   = (const float*)d_in[17];
    const float* fcb   = (const float*)d_in[18];
    const float* startp= (const float*)d_in[19];
    const float* transp= (const float*)d_in[20];
    const float* endp  = (const float*)d_in[21];
    const int*   yi    = (const int*)  d_in[22];
    float* out = (float*)d_out;

    // Opt-in to >48KB dynamic smem for the persistent recurrence kernel.
    cudaFuncSetAttribute(lstm_rec, cudaFuncAttributeMaxDynamicSharedMemorySize, REC_SMEM);

    bar_init<<<1, TT>>>();

    for (int l = 0; l < 2; l++) {
        const float* wif = (const float*)d_in[1 + l * 8 + 0];
        const float* whf = (const float*)d_in[1 + l * 8 + 1];
        const float* bif = (const float*)d_in[1 + l * 8 + 2];
        const float* bhf = (const float*)d_in[1 + l * 8 + 3];
        const float* wib = (const float*)d_in[1 + l * 8 + 4];
        const float* whb = (const float*)d_in[1 + l * 8 + 5];
        const float* bib = (const float*)d_in[1 + l * 8 + 6];
        const float* bhb = (const float*)d_in[1 + l * 8 + 7];

        prep_kernel<<<2 * G4, 256>>>(wif, whf, bif, bhf, wib, whb, bib, bhb);
        gemm_proj<<<dim3(G4 / 128, BT / 128, 2), 256>>>(bert, l);
        lstm_rec<<<dim3(48, 2), 256, REC_SMEM>>>(l);
    }
    fc_kernel<<<BT, 288>>>(fcw, fcb);
    crf_fwd<<<BB, 32>>>(yi, startp, transp, endp);
    finalize_loss<<<1, 32>>>(out);
    viterbi_kernel<<<BB, 32>>>(startp, transp, endp, out);
}

// round 13
// speedup vs baseline: 1.0843x; 1.0843x over previous
#include <cuda_runtime.h>
#include <math.h>

// Problem dims
#define BB   64
#define TT   256
#define HD   768
#define HHD  384
#define G4   1536       // 4*HHD
#define BT   (BB*TT)
#define NK   9
#define RECBLK 96       // persistent recurrence blocks (<= #SMs, all co-resident)

// Packed fp32x2 helpers (Blackwell FFMA2 path)
#define PACK2(d, x) asm("mov.b64 %0, {%1, %1};" : "=l"(d) : "r"(__float_as_uint(x)))
#define FMA2(d, a, b) asm("fma.rn.f32x2 %0, %1, %2, %0;" : "+l"(d) : "l"(a), "l"(b))
__device__ __forceinline__ float2 up2(unsigned long long v) {
    float2 r; unsigned lo = (unsigned)v, hi = (unsigned)(v >> 32);
    r.x = __uint_as_float(lo); r.y = __uint_as_float(hi); return r;
}

// ---------------- device scratch (static, no allocation) ----------------
__device__ float g_G[2 * BT * G4];        // input projections per dir (permuted gate cols)
__device__ float g_h0[BT * HD];           // layer0 output (concat fwd|bwd), row-major
__device__ float g_h1[BT * HD];           // layer1 output, row-major
__device__ float g_hT[TT * 2 * HHD * BB]; // transposed h: [t][dir][k][b] for recurrence reads
__device__ float g_Wih_p[2 * G4 * HD];    // permuted input weights  (row n' = j*4+gate)
__device__ float g_Whh_t[2 * HHD * G4];   // transposed recurrent weights [dir][k][n']
__device__ float g_bias_p[2 * G4];        // permuted bih+bhh
__device__ float g_em[BT * NK];           // emissions
__device__ float g_lp[BB];                // per-batch loglik
__device__ unsigned g_bar[2][TT];         // per-(layer,step) barrier counters

// ---------------- barrier counter zeroing (runs first in graph) ----------------
__global__ void bar_init() {
    int i = threadIdx.x;              // 256 threads
    g_bar[0][i] = 0;
    g_bar[1][i] = 0;
}

// ---------------- weight permutation: n' = j*4 + gate ----------------
__global__ void prep_kernel(const float* __restrict__ wf, const float* __restrict__ hf,
                            const float* __restrict__ bif, const float* __restrict__ bhf,
                            const float* __restrict__ wb, const float* __restrict__ hb,
                            const float* __restrict__ bib, const float* __restrict__ bhb) {
    int blk = blockIdx.x;                 // 0 .. 2*G4-1
    int dir = blk / G4;
    int np  = blk - dir * G4;
    const float* wih = dir ? wb  : wf;
    const float* whh = dir ? hb  : hf;
    const float* bi  = dir ? bib : bif;
    const float* bh  = dir ? bhb : bhf;
    int j = np >> 2, gate = np & 3;
    int r = gate * HHD + j;               // original row in [4H, *]
    float* dwi = g_Wih_p + (size_t)(dir * G4 + np) * HD;
    const float* swi = wih + (size_t)r * HD;
    for (int i = threadIdx.x; i < HD; i += 256) dwi[i] = swi[i];
    const float* swh = whh + (size_t)r * HHD;
    for (int i = threadIdx.x; i < HHD; i += 256)
        g_Whh_t[((size_t)dir * HHD + i) * G4 + np] = swh[i];   // [dir][k][n']
    if (threadIdx.x == 0) g_bias_p[dir * G4 + np] = bi[r] + bh[r];
}

// ---------------- input projection SGEMM: G = X @ Wp^T + bias ----------------
// 128x128 tile, kt=16, 256 threads, 8x8 microtile, packed-f32x2 FFMA2 core
__global__ void __launch_bounds__(256, 2) gemm_proj(const float* __restrict__ Xext, int layer) {
    __shared__ __align__(16) float As[16][132];
    __shared__ __align__(16) float Bs[16][132];
    int dir = blockIdx.z;
    const float* X    = layer ? g_h0 : Xext;
    const float* Wp   = g_Wih_p  + (size_t)dir * G4 * HD;
    const float* bias = g_bias_p + dir * G4;
    float* out        = g_G      + (size_t)dir * BT * G4;
    int m0 = blockIdx.y * 128, n0 = blockIdx.x * 128;
    int tid = threadIdx.x;
    int tx = tid & 15, ty = tid >> 4;      // tx -> n quads, ty -> m quads
    unsigned long long acc2[8][4] = {};    // [m][n-pair]; 0ull == (+0.f,+0.f)
    for (int k0 = 0; k0 < HD; k0 += 16) {
#pragma unroll
        for (int i = 0; i < 8; i++) {
            int lin = tid + i * 256; int r = lin >> 4, c = lin & 15;
            As[c][r] = X [(size_t)(m0 + r) * HD + k0 + c];
            Bs[c][r] = Wp[(size_t)(n0 + r) * HD + k0 + c];
        }
        __syncthreads();
#pragma unroll
        for (int k = 0; k < 16; k++) {
            float4 a0 = *(const float4*)&As[k][ty * 4];
            float4 a1 = *(const float4*)&As[k][ty * 4 + 64];
            ulonglong2 b0 = *(const ulonglong2*)&Bs[k][tx * 4];
            ulonglong2 b1 = *(const ulonglong2*)&Bs[k][tx * 4 + 64];
            float av[8] = {a0.x, a0.y, a0.z, a0.w, a1.x, a1.y, a1.z, a1.w};
#pragma unroll
            for (int i = 0; i < 8; i++) {
                unsigned long long av2;
                PACK2(av2, av[i]);
                FMA2(acc2[i][0], av2, b0.x);
                FMA2(acc2[i][1], av2, b0.y);
                FMA2(acc2[i][2], av2, b1.x);
                FMA2(acc2[i][3], av2, b1.y);
            }
        }
        __syncthreads();
    }
    float4 bb0 = *(const float4*)&bias[n0 + tx * 4];
    float4 bb1 = *(const float4*)&bias[n0 + tx * 4 + 64];
#pragma unroll
    for (int i = 0; i < 8; i++) {
        int m = m0 + ((i < 4) ? (ty * 4 + i) : (ty * 4 + i - 4 + 64));
        float2 p0 = up2(acc2[i][0]), p1 = up2(acc2[i][1]);
        float2 p2 = up2(acc2[i][2]), p3 = up2(acc2[i][3]);
        float4 v0 = make_float4(p0.x + bb0.x, p0.y + bb0.y, p1.x + bb0.z, p1.y + bb0.w);
        float4 v1 = make_float4(p2.x + bb1.x, p2.y + bb1.y, p3.x + bb1.z, p3.y + bb1.w);
        *(float4*)&out[(size_t)m * G4 + n0 + tx * 4]      = v0;
        *(float4*)&out[(size_t)m * G4 + n0 + tx * 4 + 64] = v1;
    }
}

// ---------------- persistent recurrence kernel (v5: v3 + FFMA2) ----------------
// 96 blocks = (48 n-tiles x 2 dirs), 128 threads (4 warps, SMSP-balanced).
// Tile per block: ALL 64 batches x 32 gate-cols x full K=384.
// Whh tile (55KB) + whole h_prev tile (104KB) resident in smem.
// Inner product uses packed f32x2 FFMA2 (w-pairs free from ulonglong2 loads,
// a splatted via mov.b64). Zero intra-step chunk syncs; 1 grid barrier/step.
#define WS 36
#define HS 68
#define REC_SMEM (HHD*WS*4 + HHD*HS*4)   /* 55296 + 104448 = 159744 B */

__global__ void __launch_bounds__(128, 1) lstm_rec(int layer) {
    extern __shared__ __align__(16) float sm[];
    float* Wsm = sm;              // [384][WS]: Wsm[k][n]
    float* Hs  = sm + HHD * WS;   // [384][HS]: Hs[k][b]

    int tid = threadIdx.x;
    int tx = tid & 7, ty = tid >> 3;   // tx: gate-quad (8), ty: batch-quad (16)
    int ntile = blockIdx.x, dir = blockIdx.y;
    int n0 = ntile * 32;
    int jj = ntile * 8 + tx;           // hidden unit index 0..383
    float* hbuf = layer ? g_h1 : g_h0;

    // one-time coalesced Whh tile load from transposed copy
    const float* Wt = g_Whh_t + (size_t)dir * HHD * G4;
    for (int idx = tid; idx < HHD * 32; idx += 128) {
        int k = idx >> 5, n = idx & 31;
        Wsm[k * WS + n] = Wt[(size_t)k * G4 + n0 + n];
    }
    __syncthreads();

    const float* Gd = g_G + (size_t)dir * BT * G4;
    float c[4] = {0.f, 0.f, 0.f, 0.f};

    for (int t = 0; t < TT; t++) {
        int tt2 = dir ? (TT - 1 - t) : t;
        unsigned long long acc2[4][2] = {};   // [batch][gate-pair]
        if (t > 0) {
            int tp = dir ? (tt2 + 1) : (tt2 - 1);
            // coalesced full-tile load: g_hT[tp][dir][k][0..63] -> Hs[k][b]
            const float4* src = (const float4*)(g_hT + (size_t)(tp * 2 + dir) * HHD * BB);
#pragma unroll
            for (int i = 0; i < 48; i++) {            // 6144 float4 / 128 thr
                int f = i * 128 + tid;
                int k = f >> 4, bq = f & 15;
                *(float4*)&Hs[k * HS + bq * 4] = src[f];
            }
            __syncthreads();
#pragma unroll 8
            for (int k = 0; k < HHD; k++) {
                ulonglong2 wp = *(const ulonglong2*)&Wsm[k * WS + tx * 4];
                float4 a = *(const float4*)&Hs[k * HS + ty * 4];
                unsigned long long a2;
                PACK2(a2, a.x); FMA2(acc2[0][0], a2, wp.x); FMA2(acc2[0][1], a2, wp.y);
                PACK2(a2, a.y); FMA2(acc2[1][0], a2, wp.x); FMA2(acc2[1][1], a2, wp.y);
                PACK2(a2, a.z); FMA2(acc2[2][0], a2, wp.x); FMA2(acc2[2][1], a2, wp.y);
                PACK2(a2, a.w); FMA2(acc2[3][0], a2, wp.x); FMA2(acc2[3][1], a2, wp.y);
            }
        }
        // gate nonlinearity + cell update (block-local; quad = i,f,g,o)
        float hv[4];
#pragma unroll
        for (int i = 0; i < 4; i++) {
            int b = ty * 4 + i;
            float2 pif = up2(acc2[i][0]);   // (i, f) partial sums
            float2 pgo = up2(acc2[i][1]);   // (g, o) partial sums
            float4 g = *(const float4*)&Gd[((size_t)(b * TT + tt2)) * G4 + n0 + tx * 4];
            g.x += pif.x; g.y += pif.y; g.z += pgo.x; g.w += pgo.y;
            float ig = 1.f / (1.f + expf(-g.x));
            float fg = 1.f / (1.f + expf(-g.y));
            float gg = tanhf(g.z);
            float og = 1.f / (1.f + expf(-g.w));
            float cn = fg * c[i] + ig * gg;
            c[i] = cn;
            hv[i] = og * tanhf(cn);
            hbuf[((size_t)(b * TT + tt2)) * HD + dir * HHD + jj] = hv[i];
        }
        *(float4*)&g_hT[((size_t)(tt2 * 2 + dir) * HHD + jj) * BB + ty * 4] =
            make_float4(hv[0], hv[1], hv[2], hv[3]);

        if (t < TT - 1) {
            __threadfence();                 // release h writes
            __syncthreads();
            if (tid == 0) {
                atomicAdd(&g_bar[layer][t], 1u);
                while (((volatile unsigned*)g_bar[layer])[t] < RECBLK) {}
                __threadfence();             // acquire
            }
            __syncthreads();
        }
    }
}

// ---------------- emission FC: em = h1 @ fc_w^T + fc_b ----------------
__global__ void fc_kernel(const float* __restrict__ fcw, const float* __restrict__ fcb) {
    int m = blockIdx.x;
    int w = threadIdx.x >> 5, lane = threadIdx.x & 31;  // 9 warps
    const float* h  = g_h1 + (size_t)m * HD;
    const float* wr = fcw + (size_t)w * HD;
    float s = 0.f;
#pragma unroll
    for (int i = 0; i < HD / 32; i++) s += h[i * 32 + lane] * wr[i * 32 + lane];
#pragma unroll
    for (int o = 16; o; o >>= 1) s += __shfl_xor_sync(0xffffffffu, s, o);
    if (lane == 0) g_em[m * NK + w] = s + fcb[w];
}

// ---------------- CRF forward (summed loglik numerator & logZ) ----------------
__global__ void crf_fwd(const int* __restrict__ y, const float* __restrict__ start,
                        const float* __restrict__ trans, const float* __restrict__ endt) {
    int b = blockIdx.x; int lane = threadIdx.x;
    int k = lane < NK ? lane : NK - 1;
    float tr[NK];
#pragma unroll
    for (int p = 0; p < NK; p++) tr[p] = trans[p * NK + k];
    const float* emb = g_em + (size_t)b * TT * NK;
    float num = 0.f;
    if (lane == 0) {
        const int* yb = y + b * TT;
        int prev = yb[0];
        num = start[prev] + emb[prev];
        for (int t = 1; t < TT; t++) {
            int yt = yb[t];
            num += trans[prev * NK + yt] + emb[t * NK + yt];
            prev = yt;
        }
        num += endt[prev];
    }
    float alpha = start[k] + emb[k];
    for (int t = 1; t < TT; t++) {
        float av[NK]; float m = -1e30f;
#pragma unroll
        for (int p = 0; p < NK; p++) {
            av[p] = __shfl_sync(0xffffffffu, alpha, p) + tr[p];
            m = fmaxf(m, av[p]);
        }
        float s = 0.f;
#pragma unroll
        for (int p = 0; p < NK; p++) s += expf(av[p] - m);
        alpha = m + logf(s) + emb[t * NK + k];
    }
    float v = alpha + endt[k];
    float m2 = -1e30f; float vs[NK];
#pragma unroll
    for (int p = 0; p < NK; p++) {
        vs[p] = __shfl_sync(0xffffffffu, v, p);
        m2 = fmaxf(m2, vs[p]);
    }
    float s2 = 0.f;
#pragma unroll
    for (int p = 0; p < NK; p++) s2 += expf(vs[p] - m2);
    if (lane == 0) g_lp[b] = num - (m2 + logf(s2));
}

__global__ void finalize_loss(float* out) {
    if (threadIdx.x == 0) {
        float s = 0.f;
        for (int i = 0; i < BB; i++) s += g_lp[i];
        out[0] = s;
    }
}

// ---------------- Viterbi decode (first-max tie-break, matches jnp.argmax) ----------------
__global__ void viterbi_kernel(const float* __restrict__ start, const float* __restrict__ trans,
                               const float* __restrict__ endt, float* __restrict__ out) {
    __shared__ int hist[TT - 1][NK];
    int b = blockIdx.x; int lane = threadIdx.x;
    int k = lane < NK ? lane : NK - 1;
    float tr[NK];
#pragma unroll
    for (int p = 0; p < NK; p++) tr[p] = trans[p * NK + k];
    const float* emb = g_em + (size_t)b * TT * NK;
    float score = start[k] + emb[k];
    for (int t = 1; t < TT; t++) {
        float best = -1e30f; int arg = 0;
#pragma unroll
        for (int p = 0; p < NK; p++) {
            float v = __shfl_sync(0xffffffffu, score, p) + tr[p];
            if (v > best) { best = v; arg = p; }
        }
        if (lane < NK) hist[t - 1][lane] = arg;
        score = best + emb[t * NK + k];
    }
    float v = score + endt[k];
    float best = -1e30f; int last = 0;
#pragma unroll
    for (int p = 0; p < NK; p++) {
        float f = __shfl_sync(0xffffffffu, v, p);
        if (f > best) { best = f; last = p; }
    }
    __syncwarp();
    if (lane == 0) {
        float* ob = out + 1 + b * TT;
        int tag = last;
        ob[TT - 1] = (float)last;
        for (int t = TT - 2; t >= 0; t--) { tag = hist[t][tag]; ob[t] = (float)tag; }
    }
}

// ---------------- launch ----------------
extern "C" void kernel_launch(void* const* d_in, const int* in_sizes, int n_in,
                              void* d_out, int out_size) {
    const float* bert  = (const float*)d_in[0];
    const float* fcw   = (const float*)d_in[17];
    const float* fcb   = (const float*)d_in[18];
    const float* startp= (const float*)d_in[19];
    const float* transp= (const float*)d_in[20];
    const float* endp  = (const float*)d_in[21];
    const int*   yi    = (const int*)  d_in[22];
    float* out = (float*)d_out;

    // Opt-in to >48KB dynamic smem for the persistent recurrence kernel.
    cudaFuncSetAttribute(lstm_rec, cudaFuncAttributeMaxDynamicSharedMemorySize, REC_SMEM);

    bar_init<<<1, TT>>>();

    for (int l = 0; l < 2; l++) {
        const float* wif = (const float*)d_in[1 + l * 8 + 0];
        const float* whf = (const float*)d_in[1 + l * 8 + 1];
        const float* bif = (const float*)d_in[1 + l * 8 + 2];
        const float* bhf = (const float*)d_in[1 + l * 8 + 3];
        const float* wib = (const float*)d_in[1 + l * 8 + 4];
        const float* whb = (const float*)d_in[1 + l * 8 + 5];
        const float* bib = (const float*)d_in[1 + l * 8 + 6];
        const float* bhb = (const float*)d_in[1 + l * 8 + 7];

        prep_kernel<<<2 * G4, 256>>>(wif, whf, bif, bhf, wib, whb, bib, bhb);
        gemm_proj<<<dim3(G4 / 128, BT / 128, 2), 256>>>(bert, l);
        lstm_rec<<<dim3(48, 2), 128, REC_SMEM>>>(l);
    }
    fc_kernel<<<BT, 288>>>(fcw, fcb);
    crf_fwd<<<BB, 32>>>(yi, startp, transp, endp);
    finalize_loss<<<1, 32>>>(out);
    viterbi_kernel<<<BB, 32>>>(startp, transp, endp, out);
}

// round 14
// speedup vs baseline: 1.0883x; 1.0037x over previous
#include <cuda_runtime.h>
#include <math.h>

// Problem dims
#define BB   64
#define TT   256
#define HD   768
#define HHD  384
#define G4   1536       // 4*HHD
#define BT   (BB*TT)
#define NK   9
#define RECBLK 96       // persistent recurrence blocks (<= #SMs, all co-resident)

// Packed fp32x2 helpers (Blackwell FFMA2 path)
#define PACK2(d, x) asm("mov.b64 %0, {%1, %1};" : "=l"(d) : "r"(__float_as_uint(x)))
#define FMA2(d, a, b) asm("fma.rn.f32x2 %0, %1, %2, %0;" : "+l"(d) : "l"(a), "l"(b))
__device__ __forceinline__ float2 up2(unsigned long long v) {
    float2 r; unsigned lo = (unsigned)v, hi = (unsigned)(v >> 32);
    r.x = __uint_as_float(lo); r.y = __uint_as_float(hi); return r;
}

// ---------------- device scratch (static, no allocation) ----------------
__device__ float g_G[2 * BT * G4];        // input projections per dir (permuted gate cols)
__device__ float g_h0[BT * HD];           // layer0 output (concat fwd|bwd), row-major
__device__ float g_h1[BT * HD];           // layer1 output, row-major
__device__ float g_hT[TT * 2 * HHD * BB]; // transposed h: [t][dir][k][b] for recurrence reads
__device__ float g_Wih_p[2 * G4 * HD];    // permuted input weights  (row n' = j*4+gate)
__device__ float g_Whh_t[2 * HHD * G4];   // transposed recurrent weights [dir][k][n']
__device__ float g_bias_p[2 * G4];        // permuted bih+bhh
__device__ float g_em[BT * NK];           // emissions
__device__ float g_lp[BB];                // per-batch loglik
__device__ unsigned g_bar[2][TT];         // per-(layer,step) barrier counters

// ---------------- barrier counter zeroing (runs first in graph) ----------------
__global__ void bar_init() {
    int i = threadIdx.x;              // 256 threads
    g_bar[0][i] = 0;
    g_bar[1][i] = 0;
}

// ---------------- weight permutation: n' = j*4 + gate ----------------
__global__ void prep_kernel(const float* __restrict__ wf, const float* __restrict__ hf,
                            const float* __restrict__ bif, const float* __restrict__ bhf,
                            const float* __restrict__ wb, const float* __restrict__ hb,
                            const float* __restrict__ bib, const float* __restrict__ bhb) {
    int blk = blockIdx.x;                 // 0 .. 2*G4-1
    int dir = blk / G4;
    int np  = blk - dir * G4;
    const float* wih = dir ? wb  : wf;
    const float* whh = dir ? hb  : hf;
    const float* bi  = dir ? bib : bif;
    const float* bh  = dir ? bhb : bhf;
    int j = np >> 2, gate = np & 3;
    int r = gate * HHD + j;               // original row in [4H, *]
    float* dwi = g_Wih_p + (size_t)(dir * G4 + np) * HD;
    const float* swi = wih + (size_t)r * HD;
    for (int i = threadIdx.x; i < HD; i += 256) dwi[i] = swi[i];
    const float* swh = whh + (size_t)r * HHD;
    for (int i = threadIdx.x; i < HHD; i += 256)
        g_Whh_t[((size_t)dir * HHD + i) * G4 + np] = swh[i];   // [dir][k][n']
    if (threadIdx.x == 0) g_bias_p[dir * G4 + np] = bi[r] + bh[r];
}

// ---------------- input projection SGEMM: G = X @ Wp^T + bias ----------------
// 128x128 tile, kt=16, 256 threads, 8x8 microtile, packed-f32x2 FFMA2 core
__global__ void __launch_bounds__(256, 2) gemm_proj(const float* __restrict__ Xext, int layer) {
    __shared__ __align__(16) float As[16][132];
    __shared__ __align__(16) float Bs[16][132];
    int dir = blockIdx.z;
    const float* X    = layer ? g_h0 : Xext;
    const float* Wp   = g_Wih_p  + (size_t)dir * G4 * HD;
    const float* bias = g_bias_p + dir * G4;
    float* out        = g_G      + (size_t)dir * BT * G4;
    int m0 = blockIdx.y * 128, n0 = blockIdx.x * 128;
    int tid = threadIdx.x;
    int tx = tid & 15, ty = tid >> 4;      // tx -> n quads, ty -> m quads
    unsigned long long acc2[8][4] = {};    // [m][n-pair]; 0ull == (+0.f,+0.f)
    for (int k0 = 0; k0 < HD; k0 += 16) {
#pragma unroll
        for (int i = 0; i < 8; i++) {
            int lin = tid + i * 256; int r = lin >> 4, c = lin & 15;
            As[c][r] = X [(size_t)(m0 + r) * HD + k0 + c];
            Bs[c][r] = Wp[(size_t)(n0 + r) * HD + k0 + c];
        }
        __syncthreads();
#pragma unroll
        for (int k = 0; k < 16; k++) {
            float4 a0 = *(const float4*)&As[k][ty * 4];
            float4 a1 = *(const float4*)&As[k][ty * 4 + 64];
            ulonglong2 b0 = *(const ulonglong2*)&Bs[k][tx * 4];
            ulonglong2 b1 = *(const ulonglong2*)&Bs[k][tx * 4 + 64];
            float av[8] = {a0.x, a0.y, a0.z, a0.w, a1.x, a1.y, a1.z, a1.w};
#pragma unroll
            for (int i = 0; i < 8; i++) {
                unsigned long long av2;
                PACK2(av2, av[i]);
                FMA2(acc2[i][0], av2, b0.x);
                FMA2(acc2[i][1], av2, b0.y);
                FMA2(acc2[i][2], av2, b1.x);
                FMA2(acc2[i][3], av2, b1.y);
            }
        }
        __syncthreads();
    }
    float4 bb0 = *(const float4*)&bias[n0 + tx * 4];
    float4 bb1 = *(const float4*)&bias[n0 + tx * 4 + 64];
#pragma unroll
    for (int i = 0; i < 8; i++) {
        int m = m0 + ((i < 4) ? (ty * 4 + i) : (ty * 4 + i - 4 + 64));
        float2 p0 = up2(acc2[i][0]), p1 = up2(acc2[i][1]);
        float2 p2 = up2(acc2[i][2]), p3 = up2(acc2[i][3]);
        float4 v0 = make_float4(p0.x + bb0.x, p0.y + bb0.y, p1.x + bb0.z, p1.y + bb0.w);
        float4 v1 = make_float4(p2.x + bb1.x, p2.y + bb1.y, p3.x + bb1.z, p3.y + bb1.w);
        *(float4*)&out[(size_t)m * G4 + n0 + tx * 4]      = v0;
        *(float4*)&out[(size_t)m * G4 + n0 + tx * 4 + 64] = v1;
    }
}

// ---------------- persistent recurrence kernel (v5: v3 + FFMA2) ----------------
// 96 blocks = (48 n-tiles x 2 dirs), 128 threads (4 warps, SMSP-balanced).
// Tile per block: ALL 64 batches x 32 gate-cols x full K=384.
// Whh tile (55KB) + whole h_prev tile (104KB) resident in smem.
// Inner product uses packed f32x2 FFMA2 (w-pairs free from ulonglong2 loads,
// a splatted via mov.b64). Zero intra-step chunk syncs; 1 grid barrier/step.
#define WS 36
#define HS 68
#define REC_SMEM (HHD*WS*4 + HHD*HS*4)   /* 55296 + 104448 = 159744 B */

__global__ void __launch_bounds__(128, 1) lstm_rec(int layer) {
    extern __shared__ __align__(16) float sm[];
    float* Wsm = sm;              // [384][WS]: Wsm[k][n]
    float* Hs  = sm + HHD * WS;   // [384][HS]: Hs[k][b]

    int tid = threadIdx.x;
    int tx = tid & 7, ty = tid >> 3;   // tx: gate-quad (8), ty: batch-quad (16)
    int ntile = blockIdx.x, dir = blockIdx.y;
    int n0 = ntile * 32;
    int jj = ntile * 8 + tx;           // hidden unit index 0..383
    float* hbuf = layer ? g_h1 : g_h0;

    // one-time coalesced Whh tile load from transposed copy
    const float* Wt = g_Whh_t + (size_t)dir * HHD * G4;
    for (int idx = tid; idx < HHD * 32; idx += 128) {
        int k = idx >> 5, n = idx & 31;
        Wsm[k * WS + n] = Wt[(size_t)k * G4 + n0 + n];
    }
    __syncthreads();

    const float* Gd = g_G + (size_t)dir * BT * G4;
    float c[4] = {0.f, 0.f, 0.f, 0.f};

    for (int t = 0; t < TT; t++) {
        int tt2 = dir ? (TT - 1 - t) : t;
        unsigned long long acc2[4][2] = {};   // [batch][gate-pair]
        if (t > 0) {
            int tp = dir ? (tt2 + 1) : (tt2 - 1);
            // coalesced full-tile load: g_hT[tp][dir][k][0..63] -> Hs[k][b]
            const float4* src = (const float4*)(g_hT + (size_t)(tp * 2 + dir) * HHD * BB);
#pragma unroll
            for (int i = 0; i < 48; i++) {            // 6144 float4 / 128 thr
                int f = i * 128 + tid;
                int k = f >> 4, bq = f & 15;
                *(float4*)&Hs[k * HS + bq * 4] = src[f];
            }
            __syncthreads();
#pragma unroll 8
            for (int k = 0; k < HHD; k++) {
                ulonglong2 wp = *(const ulonglong2*)&Wsm[k * WS + tx * 4];
                float4 a = *(const float4*)&Hs[k * HS + ty * 4];
                unsigned long long a2;
                PACK2(a2, a.x); FMA2(acc2[0][0], a2, wp.x); FMA2(acc2[0][1], a2, wp.y);
                PACK2(a2, a.y); FMA2(acc2[1][0], a2, wp.x); FMA2(acc2[1][1], a2, wp.y);
                PACK2(a2, a.z); FMA2(acc2[2][0], a2, wp.x); FMA2(acc2[2][1], a2, wp.y);
                PACK2(a2, a.w); FMA2(acc2[3][0], a2, wp.x); FMA2(acc2[3][1], a2, wp.y);
            }
        }
        // gate nonlinearity + cell update (block-local; quad = i,f,g,o)
        float hv[4];
#pragma unroll
        for (int i = 0; i < 4; i++) {
            int b = ty * 4 + i;
            float2 pif = up2(acc2[i][0]);   // (i, f) partial sums
            float2 pgo = up2(acc2[i][1]);   // (g, o) partial sums
            float4 g = *(const float4*)&Gd[((size_t)(b * TT + tt2)) * G4 + n0 + tx * 4];
            g.x += pif.x; g.y += pif.y; g.z += pgo.x; g.w += pgo.y;
            float ig = 1.f / (1.f + expf(-g.x));
            float fg = 1.f / (1.f + expf(-g.y));
            float gg = tanhf(g.z);
            float og = 1.f / (1.f + expf(-g.w));
            float cn = fg * c[i] + ig * gg;
            c[i] = cn;
            hv[i] = og * tanhf(cn);
            hbuf[((size_t)(b * TT + tt2)) * HD + dir * HHD + jj] = hv[i];
        }
        *(float4*)&g_hT[((size_t)(tt2 * 2 + dir) * HHD + jj) * BB + ty * 4] =
            make_float4(hv[0], hv[1], hv[2], hv[3]);

        if (t < TT - 1) {
            __threadfence();                 // release h writes
            __syncthreads();
            if (tid == 0) {
                atomicAdd(&g_bar[layer][t], 1u);
                while (((volatile unsigned*)g_bar[layer])[t] < RECBLK) {}
                __threadfence();             // acquire
            }
            __syncthreads();
        }
    }
}

// ---------------- emission FC: em = h1 @ fc_w^T + fc_b ----------------
__global__ void fc_kernel(const float* __restrict__ fcw, const float* __restrict__ fcb) {
    int m = blockIdx.x;
    int w = threadIdx.x >> 5, lane = threadIdx.x & 31;  // 9 warps
    const float* h  = g_h1 + (size_t)m * HD;
    const float* wr = fcw + (size_t)w * HD;
    float s = 0.f;
#pragma unroll
    for (int i = 0; i < HD / 32; i++) s += h[i * 32 + lane] * wr[i * 32 + lane];
#pragma unroll
    for (int o = 16; o; o >>= 1) s += __shfl_xor_sync(0xffffffffu, s, o);
    if (lane == 0) g_em[m * NK + w] = s + fcb[w];
}

// ---------------- CRF forward (summed loglik numerator & logZ) ----------------
__global__ void crf_fwd(const int* __restrict__ y, const float* __restrict__ start,
                        const float* __restrict__ trans, const float* __restrict__ endt) {
    int b = blockIdx.x; int lane = threadIdx.x;
    int k = lane < NK ? lane : NK - 1;
    float tr[NK];
#pragma unroll
    for (int p = 0; p < NK; p++) tr[p] = trans[p * NK + k];
    const float* emb = g_em + (size_t)b * TT * NK;
    float num = 0.f;
    if (lane == 0) {
        const int* yb = y + b * TT;
        int prev = yb[0];
        num = start[prev] + emb[prev];
        for (int t = 1; t < TT; t++) {
            int yt = yb[t];
            num += trans[prev * NK + yt] + emb[t * NK + yt];
            prev = yt;
        }
        num += endt[prev];
    }
    float alpha = start[k] + emb[k];
    for (int t = 1; t < TT; t++) {
        float av[NK]; float m = -1e30f;
#pragma unroll
        for (int p = 0; p < NK; p++) {
            av[p] = __shfl_sync(0xffffffffu, alpha, p) + tr[p];
            m = fmaxf(m, av[p]);
        }
        float s = 0.f;
#pragma unroll
        for (int p = 0; p < NK; p++) s += expf(av[p] - m);
        alpha = m + logf(s) + emb[t * NK + k];
    }
    float v = alpha + endt[k];
    float m2 = -1e30f; float vs[NK];
#pragma unroll
    for (int p = 0; p < NK; p++) {
        vs[p] = __shfl_sync(0xffffffffu, v, p);
        m2 = fmaxf(m2, vs[p]);
    }
    float s2 = 0.f;
#pragma unroll
    for (int p = 0; p < NK; p++) s2 += expf(vs[p] - m2);
    if (lane == 0) g_lp[b] = num - (m2 + logf(s2));
}

__global__ void finalize_loss(float* out) {
    if (threadIdx.x == 0) {
        float s = 0.f;
        for (int i = 0; i < BB; i++) s += g_lp[i];
        out[0] = s;
    }
}

// ---------------- Viterbi decode (first-max tie-break, matches jnp.argmax) ----------------
__global__ void viterbi_kernel(const float* __restrict__ start, const float* __restrict__ trans,
                               const float* __restrict__ endt, float* __restrict__ out) {
    __shared__ int hist[TT - 1][NK];
    int b = blockIdx.x; int lane = threadIdx.x;
    int k = lane < NK ? lane : NK - 1;
    float tr[NK];
#pragma unroll
    for (int p = 0; p < NK; p++) tr[p] = trans[p * NK + k];
    const float* emb = g_em + (size_t)b * TT * NK;
    float score = start[k] + emb[k];
    for (int t = 1; t < TT; t++) {
        float best = -1e30f; int arg = 0;
#pragma unroll
        for (int p = 0; p < NK; p++) {
            float v = __shfl_sync(0xffffffffu, score, p) + tr[p];
            if (v > best) { best = v; arg = p; }
        }
        if (lane < NK) hist[t - 1][lane] = arg;
        score = best + emb[t * NK + k];
    }
    float v = score + endt[k];
    float best = -1e30f; int last = 0;
#pragma unroll
    for (int p = 0; p < NK; p++) {
        float f = __shfl_sync(0xffffffffu, v, p);
        if (f > best) { best = f; last = p; }
    }
    __syncwarp();
    if (lane == 0) {
        float* ob = out + 1 + b * TT;
        int tag = last;
        ob[TT - 1] = (float)last;
        for (int t = TT - 2; t >= 0; t--) { tag = hist[t][tag]; ob[t] = (float)tag; }
    }
}

// ---------------- launch ----------------
extern "C" void kernel_launch(void* const* d_in, const int* in_sizes, int n_in,
                              void* d_out, int out_size) {
    const float* bert  = (const float*)d_in[0];
    const float* fcw   = (const float*)d_in[17];
    const float* fcb   = (const float*)d_in[18];
    const float* startp= (const float*)d_in[19];
    const float* transp= (const float*)d_in[20];
    const float* endp  = (const float*)d_in[21];
    const int*   yi    = (const int*)  d_in[22];
    float* out = (float*)d_out;

    // Opt-in to >48KB dynamic smem for the persistent recurrence kernel.
    cudaFuncSetAttribute(lstm_rec, cudaFuncAttributeMaxDynamicSharedMemorySize, REC_SMEM);

    bar_init<<<1, TT>>>();

    for (int l = 0; l < 2; l++) {
        const float* wif = (const float*)d_in[1 + l * 8 + 0];
        const float* whf = (const float*)d_in[1 + l * 8 + 1];
        const float* bif = (const float*)d_in[1 + l * 8 + 2];
        const float* bhf = (const float*)d_in[1 + l * 8 + 3];
        const float* wib = (const float*)d_in[1 + l * 8 + 4];
        const float* whb = (const float*)d_in[1 + l * 8 + 5];
        const float* bib = (const float*)d_in[1 + l * 8 + 6];
        const float* bhb = (const float*)d_in[1 + l * 8 + 7];

        prep_kernel<<<2 * G4, 256>>>(wif, whf, bif, bhf, wib, whb, bib, bhb);
        gemm_proj<<<dim3(G4 / 128, BT / 128, 2), 256>>>(bert, l);
        lstm_rec<<<dim3(48, 2), 128, REC_SMEM>>>(l);
    }
    fc_kernel<<<BT, 288>>>(fcw, fcb);
    crf_fwd<<<BB, 32>>>(yi, startp, transp, endp);
    finalize_loss<<<1, 32>>>(out);
    viterbi_kernel<<<BB, 32>>>(startp, transp, endp, out);
}